// round 3
// baseline (speedup 1.0000x reference)
#include <cuda_runtime.h>
#include <cuda_bf16.h>

// CurricularFace loss:
//   loss = mean_r( logsumexp_j(S*m_rj) - S*ftl_r )
// Single streaming pass over cos_theta [N, C] fp32 (819 MB) -> memory bound.
// logsumexp shift B = S*max(t+1, 1) is an analytic upper bound on S*m, so no
// max pass is needed; the label column is fixed up with a per-row exp-space
// correction computed in a tiny prep kernel.

#define NMAX 2048

__device__ float g_ctm[NMAX];      // cos_theta_m per row (hard-example threshold)
__device__ float g_sftl[NMAX];     // S * final_target_logit per row
__device__ float g_corr[NMAX];     // exp-space correction for the label column
__device__ float g_rowloss[NMAX];  // per-row loss terms

__device__ __forceinline__ float ex2f(float x) {
    float y;
    asm("ex2.approx.ftz.f32 %0, %1;" : "=f"(y) : "f"(x));
    return y;
}

// ---------------------------------------------------------------------------
// Kernel 1: per-row prep (gather target logit, margin math, label correction)
// ---------------------------------------------------------------------------
__global__ void prep_kernel(const float* __restrict__ cosm,
                            const int* __restrict__ labels,   // harness downcasts int64 -> int32
                            const float* __restrict__ t,
                            int n, int C) {
    int i = blockIdx.x * blockDim.x + threadIdx.x;
    if (i >= n) return;

    const float S      = 64.0f;
    const float COS_M  = 0.87758255f;    // cos(0.5)
    const float SIN_M  = 0.47942555f;    // sin(0.5)
    const float THRESH = -0.87758255f;   // cos(pi - 0.5)
    const float MM     = 0.23971277f;    // sin(pi-0.5)*0.5

    int lab = labels[i];
    lab = min(max(lab, 0), C - 1);       // defensive: never fault on a bad label
    float tl = cosm[(long long)i * C + lab];
    tl = fminf(fmaxf(tl, -1.0f), 1.0f);

    float st  = sqrtf(fmaxf(1.0f - tl * tl, 0.0f));
    float ctm = tl * COS_M - st * SIN_M;
    float ftl = (tl > THRESH) ? ctm : (tl - MM);

    float tv = t[0];
    float B  = S * fmaxf(tv + 1.0f, 1.0f);

    // Value the main pass will (wrongly) compute at the label column:
    float h = tl * (tv + tl);
    float m = (tl > ctm) ? h : tl;

    // corr = correct label term - regular-formula label term (exp space, shifted by B)
    float corr = expf(S * ftl - B) - expf(S * m - B);

    g_ctm[i]  = ctm;
    g_sftl[i] = S * ftl;
    g_corr[i] = corr;
}

// ---------------------------------------------------------------------------
// Kernel 2: one block per row, streaming sum of exp(S*m - B)
// ---------------------------------------------------------------------------
__global__ __launch_bounds__(512) void row_kernel(const float* __restrict__ cosm,
                                                  const float* __restrict__ t,
                                                  int C) {
    const int row = blockIdx.x;
    const float ctm = g_ctm[row];
    const float tv  = t[0];
    const float LOG2E = 1.44269504f;
    const float B   = 64.0f * fmaxf(tv + 1.0f, 1.0f);
    const float K   = 64.0f * LOG2E;     // scale into log2 domain
    const float OFF = -B * LOG2E;

    const float4* __restrict__ p =
        reinterpret_cast<const float4*>(cosm + (long long)row * C);
    const int C4 = C >> 2;

    float sum = 0.0f;
    #pragma unroll 4
    for (int i = threadIdx.x; i < C4; i += 512) {
        float4 v = p[i];
        {
            float c = fminf(fmaxf(v.x, -1.0f), 1.0f);
            float m = (c > ctm) ? fmaf(c, c, c * tv) : c;
            sum += ex2f(fmaf(m, K, OFF));
        }
        {
            float c = fminf(fmaxf(v.y, -1.0f), 1.0f);
            float m = (c > ctm) ? fmaf(c, c, c * tv) : c;
            sum += ex2f(fmaf(m, K, OFF));
        }
        {
            float c = fminf(fmaxf(v.z, -1.0f), 1.0f);
            float m = (c > ctm) ? fmaf(c, c, c * tv) : c;
            sum += ex2f(fmaf(m, K, OFF));
        }
        {
            float c = fminf(fmaxf(v.w, -1.0f), 1.0f);
            float m = (c > ctm) ? fmaf(c, c, c * tv) : c;
            sum += ex2f(fmaf(m, K, OFF));
        }
    }
    // tail (C not multiple of 4)
    for (int i = (C4 << 2) + threadIdx.x; i < C; i += 512) {
        float c = fminf(fmaxf(cosm[(long long)row * C + i], -1.0f), 1.0f);
        float m = (c > ctm) ? fmaf(c, c, c * tv) : c;
        sum += ex2f(fmaf(m, K, OFF));
    }

    // block reduce (16 warps)
    __shared__ float smem[16];
    #pragma unroll
    for (int off = 16; off > 0; off >>= 1)
        sum += __shfl_down_sync(0xFFFFFFFFu, sum, off);
    int warp = threadIdx.x >> 5;
    int lane = threadIdx.x & 31;
    if (lane == 0) smem[warp] = sum;
    __syncthreads();
    if (warp == 0) {
        float s = (lane < 16) ? smem[lane] : 0.0f;
        #pragma unroll
        for (int off = 8; off > 0; off >>= 1)
            s += __shfl_down_sync(0xFFFFFFFFu, s, off);
        if (lane == 0) {
            float total = s + g_corr[row];
            // row loss = logsumexp - S*ftl = log(total) + B - S*ftl
            g_rowloss[row] = logf(total) + B - g_sftl[row];
        }
    }
}

// ---------------------------------------------------------------------------
// Kernel 3: deterministic final reduction over rows
// ---------------------------------------------------------------------------
__global__ __launch_bounds__(1024) void final_kernel(float* __restrict__ out, int n) {
    __shared__ float smem[32];
    float sum = 0.0f;
    for (int i = threadIdx.x; i < n; i += 1024)
        sum += g_rowloss[i];
    #pragma unroll
    for (int off = 16; off > 0; off >>= 1)
        sum += __shfl_down_sync(0xFFFFFFFFu, sum, off);
    int warp = threadIdx.x >> 5;
    int lane = threadIdx.x & 31;
    if (lane == 0) smem[warp] = sum;
    __syncthreads();
    if (warp == 0) {
        float s = (lane < 32) ? smem[lane] : 0.0f;
        #pragma unroll
        for (int off = 16; off > 0; off >>= 1)
            s += __shfl_down_sync(0xFFFFFFFFu, s, off);
        if (lane == 0) out[0] = s / (float)n;
    }
}

extern "C" void kernel_launch(void* const* d_in, const int* in_sizes, int n_in,
                              void* d_out, int out_size) {
    const float* cosm   = (const float*)d_in[0];
    const int*   labels = (const int*)d_in[1];
    const float* t      = (const float*)d_in[2];
    float*       out    = (float*)d_out;

    int n = in_sizes[1];              // number of rows (labels count)
    int C = in_sizes[0] / n;          // columns

    prep_kernel<<<(n + 255) / 256, 256>>>(cosm, labels, t, n, C);
    row_kernel<<<n, 512>>>(cosm, t, C);
    final_kernel<<<1, 1024>>>(out, n);
}